// round 15
// baseline (speedup 1.0000x reference)
#include <cuda_runtime.h>

typedef unsigned long long u64;

// Shapes (fixed by the problem)
#define BB 8
#define CC 64
#define HH 32
#define WW 32
#define OO 32
#define QQ 8

// HW tanh sigmoid: sigmoid(x) = 0.5*tanh(0.5x) + 0.5  (MUFU.TANH, sm_75+)
__device__ __forceinline__ float sigmoidf(float x) {
    float t;
    asm("tanh.approx.f32 %0, %1;" : "=f"(t) : "f"(0.5f * x));
    return fmaf(0.5f, t, 0.5f);
}

// ---- packed f32x2 helpers (Blackwell FFMA2 path, PTX-only) ----
__device__ __forceinline__ u64 fma2(u64 a, u64 b, u64 c) {
    u64 d; asm("fma.rn.f32x2 %0, %1, %2, %3;" : "=l"(d) : "l"(a), "l"(b), "l"(c)); return d;
}
__device__ __forceinline__ u64 sub2(u64 a, u64 b) {
    u64 d; asm("sub.rn.f32x2 %0, %1, %2;" : "=l"(d) : "l"(a), "l"(b)); return d;
}
__device__ __forceinline__ u64 pack2(float lo, float hi) {
    u64 r; asm("mov.b64 %0, {%1, %2};" : "=l"(r) : "f"(lo), "f"(hi)); return r;
}
__device__ __forceinline__ float2 unpack2(u64 v) {
    float2 f; asm("mov.b64 {%0, %1}, %2;" : "=f"(f.x), "=f"(f.y) : "l"(v)); return f;
}
// Packed sigmoid: mul2 + 2x MUFU.TANH + fma2
__device__ __forceinline__ u64 sig2(u64 v) {
    const u64 HALF2 = 0x3F0000003F000000ull;  // (0.5f, 0.5f)
    u64 h; asm("mul.rn.f32x2 %0, %1, %2;" : "=l"(h) : "l"(v), "l"(HALF2));
    float2 f = unpack2(h);
    float t0, t1;
    asm("tanh.approx.f32 %0, %1;" : "=f"(t0) : "f"(f.x));
    asm("tanh.approx.f32 %0, %1;" : "=f"(t1) : "f"(f.y));
    return fma2(pack2(t0, t1), HALF2, HALF2);
}

// Packed 4-input multilinear LUT, bilinear-coefficient form.
// w: 16 u64 (dup-pair): [a0..a3, b0..b3, c0..c3, d0..d3] for corners k of
// (bit1,bit0): u_k = fma(x3, fma(x2,d,c), fma(x2,b,a)); then bits 1,0.
__device__ __forceinline__ u64 lut4p(const u64* __restrict__ w,
                                     u64 x0, u64 x1, u64 x2, u64 x3) {
    const ulonglong2* wv = (const ulonglong2*)w;
    ulonglong2 a01 = wv[0], a23 = wv[1], b01 = wv[2], b23 = wv[3];
    ulonglong2 c01 = wv[4], c23 = wv[5], d01 = wv[6], d23 = wv[7];
    u64 u0 = fma2(x3, fma2(x2, d01.x, c01.x), fma2(x2, b01.x, a01.x));
    u64 u1 = fma2(x3, fma2(x2, d01.y, c01.y), fma2(x2, b01.y, a01.y));
    u64 u2 = fma2(x3, fma2(x2, d23.x, c23.x), fma2(x2, b23.x, a23.x));
    u64 u3 = fma2(x3, fma2(x2, d23.y, c23.y), fma2(x2, b23.y, a23.y));
    u64 t0 = fma2(x1, sub2(u2, u0), u0);
    u64 t1 = fma2(x1, sub2(u3, u1), u1);
    return fma2(x0, sub2(t1, t0), t0);
}

// Input t maps to (q = t/9, k = t%9, ky = k/3, kx = k%3); tile strides 180/18/1.
#define XINB(B, t) (B)[((t) / 9) * 180 + (((t) % 9) / 3) * 18 + ((t) % 9) % 3]

// Block = (quarter, bb, o): 8 rows x 32 cols, 64 threads, TWO pixel-pair
// streams per thread (rows h0 and h0+4, cols c/c+16 packed in f32x2).
// 7 CTAs/SM resident (448 thr) = single wave; reg budget 146/thread.
// The 2 streams share all weight LDS (CSE) and give ILP~2 on every chain.
//
// ws2 (u64 = dup float pair) layout:
//  [0..287]    w0: 18 luts x 16 (abcd form)
//  [288..351]  w1 tables 0..3 (abcd form)
//  [352..367]  w2 table 0 (abcd form)          (lut index 22)
//  [368..371]  folded w1 t4 bilinear {A,B,C,D}  (bit0=cur16, bit1=cur17)
//  [372..375]  folded w3 bilinear    {A,B,C,D}  (bit0=n20, bit1=n21)
//  [376..377]  folded w2 t1 linear   {base, diff}
__global__ __launch_bounds__(64, 7) void lut_kernel(
    const float* __restrict__ x,
    const float* __restrict__ w0, const float* __restrict__ w1,
    const float* __restrict__ w2, const float* __restrict__ w3,
    const int* __restrict__ ci, float* __restrict__ out)
{
    __shared__ u64 tilep[QQ][10][18];   // (col j-1, col j+15) pairs, rows row0-1..row0+8
    __shared__ __align__(16) u64 ws2[384];
    __shared__ int ch[QQ];

    const int quarter = blockIdx.x;
    const int bb = blockIdx.y;
    const int o = blockIdx.z;
    const int tid = threadIdx.x;

    if (tid < QQ) ch[tid] = ci[o * QQ + tid];

    // Full luts in abcd (bilinear-coefficient) form, duplicated into pairs.
    for (int idx = tid; idx < 368; idx += 64) {
        const int l = idx >> 4, j = idx & 15;
        const float* src;
        if (l < 18)      src = w0 + o * 288 + l * 16;
        else if (l < 22) src = w1 + o * 80 + (l - 18) * 16;
        else             src = w2 + o * 32;
        const int k = j & 3, g = j >> 2;
        float v;
        if (g == 0)      v = src[k];
        else if (g == 1) v = src[k + 4] - src[k];
        else if (g == 2) v = src[k + 8] - src[k];
        else             v = src[k + 12] - src[k + 8] - src[k + 4] + src[k];
        ws2[idx] = pack2(v, v);
    }
    // Folded tables (0.5-pinned inputs averaged out), disjoint slots.
    if (tid == 0) {            // w1 table 4: avg bits 2,3 -> bilinear abcd
        const float* s = w1 + o * 80 + 64;
        float cb0 = 0.25f * (s[0] + s[4] + s[8]  + s[12]);
        float cb1 = 0.25f * (s[1] + s[5] + s[9]  + s[13]);
        float cb2 = 0.25f * (s[2] + s[6] + s[10] + s[14]);
        float cb3 = 0.25f * (s[3] + s[7] + s[11] + s[15]);
        ws2[368] = pack2(cb0, cb0);
        ws2[369] = pack2(cb1 - cb0, cb1 - cb0);
        ws2[370] = pack2(cb2 - cb0, cb2 - cb0);
        float d = cb3 - cb2 - cb1 + cb0;
        ws2[371] = pack2(d, d);
    } else if (tid == 1) {     // w3: avg bits 2,3 -> bilinear abcd
        const float* s = w3 + o * 16;
        float cb0 = 0.25f * (s[0] + s[4] + s[8]  + s[12]);
        float cb1 = 0.25f * (s[1] + s[5] + s[9]  + s[13]);
        float cb2 = 0.25f * (s[2] + s[6] + s[10] + s[14]);
        float cb3 = 0.25f * (s[3] + s[7] + s[11] + s[15]);
        ws2[372] = pack2(cb0, cb0);
        ws2[373] = pack2(cb1 - cb0, cb1 - cb0);
        ws2[374] = pack2(cb2 - cb0, cb2 - cb0);
        float d = cb3 - cb2 - cb1 + cb0;
        ws2[375] = pack2(d, d);
    } else if (tid == 2) {     // w2 table 1: avg bits 1,2,3 -> linear
        const float* s = w2 + o * 32 + 16;
        float c0 = 0.f, c1 = 0.f;
        #pragma unroll
        for (int k = 0; k < 8; k++) { c0 += s[2 * k]; c1 += s[2 * k + 1]; }
        c0 *= 0.125f; c1 *= 0.125f;
        ws2[376] = pack2(c0, c0); ws2[377] = pack2(c1 - c0, c1 - c0);
    }
    __syncthreads();

    const int row0 = quarter * 8;

    // Fill paired tile, column-walk. Thread (fq = tid>>4 in 0..3, fc = tid&15)
    // covers q = fq and q = fq+4; cols fc (+ straggler cols 16,17 on fc=14,15).
    // Slot [q][r][c] holds (col c-1, col c+15) of row row0-1+r; OOB -> 0.5.
    {
        const int fq = tid >> 4;
        const int fc = tid & 15;
        #pragma unroll
        for (int qq = 0; qq < 2; qq++) {
            const int q = fq + qq * 4;
            const float* gb = x + ((bb * CC + ch[q]) * HH + (row0 - 1)) * WW;
            auto fill_col = [&](int c) {
                const bool okA = (c >= 1);
                const bool okB = (c + 15 < WW);
                const float* pA = gb + (c - 1);
                const float* pB = gb + (c + 15);
                u64* sp = &tilep[q][0][c];
                #pragma unroll
                for (int r = 0; r < 10; r++) {
                    const int gh = row0 - 1 + r;
                    const bool okR = ((unsigned)gh < HH);
                    float vA = 0.5f, vB = 0.5f;
                    if (okA && okR) vA = sigmoidf(pA[r * WW]);
                    if (okB && okR) vB = sigmoidf(pB[r * WW]);
                    sp[r * 18] = pack2(vA, vB);
                }
            };
            fill_col(fc);
            if (fc >= 14) fill_col(fc + 2);   // cols 16, 17
        }
    }
    __syncthreads();

    const int h0 = tid >> 4;          // stream0 row 0..3 (stream1 = h0+4)
    const int c  = tid & 15;          // pair cols (c, c+16)
    const u64* tb[2] = { &tilep[0][h0][c], &tilep[0][h0 + 4][c] };

    // Levels 0+1, two streams interleaved (shared weight loads, ILP 2).
    u64 n1[2][5];
    #pragma unroll
    for (int l1 = 0; l1 < 4; l1++) {
        u64 xs[2][4];
        #pragma unroll
        for (int j = 0; j < 4; j++) {
            const int l = 4 * l1 + j;
            #pragma unroll
            for (int s = 0; s < 2; s++) {
                xs[s][j] = sig2(lut4p(&ws2[l * 16],
                                      XINB(tb[s], 4 * l + 0), XINB(tb[s], 4 * l + 1),
                                      XINB(tb[s], 4 * l + 2), XINB(tb[s], 4 * l + 3)));
            }
        }
        #pragma unroll
        for (int s = 0; s < 2; s++)
            n1[s][l1] = sig2(lut4p(&ws2[(18 + l1) * 16],
                                   xs[s][0], xs[s][1], xs[s][2], xs[s][3]));
    }
    {
        u64 a[2], b[2];
        #pragma unroll
        for (int s = 0; s < 2; s++)
            a[s] = sig2(lut4p(&ws2[16 * 16], XINB(tb[s], 64), XINB(tb[s], 65),
                                             XINB(tb[s], 66), XINB(tb[s], 67)));
        #pragma unroll
        for (int s = 0; s < 2; s++)
            b[s] = sig2(lut4p(&ws2[17 * 16], XINB(tb[s], 68), XINB(tb[s], 69),
                                             XINB(tb[s], 70), XINB(tb[s], 71)));
        #pragma unroll
        for (int s = 0; s < 2; s++)
            n1[s][4] = sig2(fma2(b[s], fma2(a[s], ws2[371], ws2[370]),
                                       fma2(a[s], ws2[369], ws2[368])));
    }

    // Levels 2+3, both streams.
    #pragma unroll
    for (int s = 0; s < 2; s++) {
        u64 n20 = sig2(lut4p(&ws2[22 * 16], n1[s][0], n1[s][1], n1[s][2], n1[s][3]));
        u64 n21 = sig2(fma2(n1[s][4], ws2[377], ws2[376]));
        u64 res = fma2(n21, fma2(n20, ws2[375], ws2[374]),
                            fma2(n20, ws2[373], ws2[372]));
        float2 r = unpack2(res);
        float* op = out + ((bb * OO + o) * HH + row0 + h0 + s * 4) * WW;
        op[c] = r.x;
        op[c + 16] = r.y;
    }
}

extern "C" void kernel_launch(void* const* d_in, const int* in_sizes, int n_in,
                              void* d_out, int out_size) {
    const float* x  = (const float*)d_in[0];
    const float* w0 = (const float*)d_in[1];
    const float* w1 = (const float*)d_in[2];
    const float* w2 = (const float*)d_in[3];
    const float* w3 = (const float*)d_in[4];
    const int*   ci = (const int*)d_in[5];
    float* out = (float*)d_out;

    lut_kernel<<<dim3(4, BB, OO), 64>>>(x, w0, w1, w2, w3, ci, out);
}